// round 2
// baseline (speedup 1.0000x reference)
#include <cuda_runtime.h>
#include <cuda_bf16.h>
#include <stdint.h>

// Problem constants
#define NN 10000          // nodes
#define EE 160000         // edges
#define DD 512            // feature dim (in == out)
#define DV4 (DD/4)        // 128 float4 per row

// ---------------- device scratch (no allocs allowed) ----------------
__device__ float g_dinv[NN];          // deg -> rsqrt(deg)
__device__ int   g_counts[NN];        // in-degree (by col)
__device__ int   g_offsets[NN + 1];   // CSR offsets
__device__ int   g_cursor[NN];        // fill cursors
__device__ int   g_esorted[EE];       // edge ids sorted by target
__device__ float g_h[(size_t)NN * DD];// h = x @ W  (~20.5 MB)

// ---------------- kernel 1: init ----------------
__global__ void init_kernel() {
    int i = blockIdx.x * blockDim.x + threadIdx.x;
    if (i < NN) {
        g_dinv[i]   = 1.0f;   // self-loop weight 1.0 pre-seeded into deg
        g_counts[i] = 0;
    }
}

// ---------------- kernel 2: degree + in-count ----------------
__global__ void deg_kernel(const int* __restrict__ eidx,
                           const float* __restrict__ ew) {
    int e = blockIdx.x * blockDim.x + threadIdx.x;
    if (e < EE) {
        int c = eidx[EE + e];                   // col (target)
        atomicAdd(&g_dinv[c], ew[e]);           // deg accumulates here
        atomicAdd(&g_counts[c], 1);
    }
}

// ---------------- kernel 3: deg -> rsqrt(deg) ----------------
__global__ void dinv_kernel() {
    int i = blockIdx.x * blockDim.x + threadIdx.x;
    if (i < NN) {
        float d = g_dinv[i];                    // >= 1.0 always
        g_dinv[i] = rsqrtf(d);
    }
}

// ---------------- kernel 4: exclusive scan of counts (1 block) ----------------
__global__ void scan_kernel() {
    __shared__ int s[1024];
    const int CH = (NN + 1023) / 1024;          // 10
    int t = threadIdx.x;
    int base = t * CH;
    int local[CH];
    int sum = 0;
#pragma unroll
    for (int i = 0; i < CH; ++i) {
        int idx = base + i;
        local[i] = (idx < NN) ? g_counts[idx] : 0;
        sum += local[i];
    }
    s[t] = sum;
    __syncthreads();
    // Kogge-Stone inclusive scan over 1024 partials
#pragma unroll
    for (int off = 1; off < 1024; off <<= 1) {
        int v = (t >= off) ? s[t - off] : 0;
        __syncthreads();
        s[t] += v;
        __syncthreads();
    }
    int run = s[t] - sum;                       // exclusive prefix
#pragma unroll
    for (int i = 0; i < CH; ++i) {
        int idx = base + i;
        if (idx < NN) {
            g_offsets[idx] = run;
            g_cursor[idx]  = run;
            run += local[i];
        }
    }
    if (t == 1023) g_offsets[NN] = s[1023];     // == EE
}

// ---------------- kernel 5: CSR fill ----------------
__global__ void fill_kernel(const int* __restrict__ eidx) {
    int e = blockIdx.x * blockDim.x + threadIdx.x;
    if (e < EE) {
        int c = eidx[EE + e];
        int p = atomicAdd(&g_cursor[c], 1);
        g_esorted[p] = e;
    }
}

// ---------------- kernel 6: SGEMM h = x @ W  (M=NN, K=DD, N=DD) ----------------
#define BM 128
#define BN 128
#define BK 8
#define TM 8
#define TN 8

__global__ __launch_bounds__(256, 2)
void sgemm_kernel(const float* __restrict__ A,   // [NN, DD]
                  const float* __restrict__ B) { // [DD, DD]
    __shared__ float As[BK][BM];
    __shared__ float Bs[BK][BN];

    const int bx = blockIdx.x;          // N tile
    const int by = blockIdx.y;          // M tile
    const int tid = threadIdx.x;        // 0..255

    const int tx = (tid % 16) * TN;     // col in tile
    const int ty = (tid / 16) * TM;     // row in tile

    // A loads: 128x8 tile, one float4 per thread
    const int aRow = tid >> 1;          // 0..127
    const int aCol = (tid & 1) * 4;     // 0 or 4
    // B loads: 8x128 tile, one float4 per thread
    const int bRow = tid >> 5;          // 0..7
    const int bCol = (tid & 31) * 4;

    const int mBase = by * BM;
    const float* Ab = A + (size_t)mBase * DD;
    const float* Bb = B + bx * BN;

    float acc[TM][TN];
#pragma unroll
    for (int i = 0; i < TM; ++i)
#pragma unroll
        for (int j = 0; j < TN; ++j) acc[i][j] = 0.0f;

    for (int k0 = 0; k0 < DD; k0 += BK) {
        float4 av;
        if (mBase + aRow < NN)
            av = *(const float4*)(Ab + (size_t)aRow * DD + k0 + aCol);
        else
            av = make_float4(0.f, 0.f, 0.f, 0.f);
        As[aCol + 0][aRow] = av.x;
        As[aCol + 1][aRow] = av.y;
        As[aCol + 2][aRow] = av.z;
        As[aCol + 3][aRow] = av.w;

        float4 bv = *(const float4*)(Bb + (size_t)(k0 + bRow) * DD + bCol);
        *(float4*)&Bs[bRow][bCol] = bv;

        __syncthreads();

#pragma unroll
        for (int kk = 0; kk < BK; ++kk) {
            float4 ra0 = *(const float4*)&As[kk][ty];
            float4 ra1 = *(const float4*)&As[kk][ty + 4];
            float4 rb0 = *(const float4*)&Bs[kk][tx];
            float4 rb1 = *(const float4*)&Bs[kk][tx + 4];
            float ra[TM] = {ra0.x, ra0.y, ra0.z, ra0.w, ra1.x, ra1.y, ra1.z, ra1.w};
            float rb[TN] = {rb0.x, rb0.y, rb0.z, rb0.w, rb1.x, rb1.y, rb1.z, rb1.w};
#pragma unroll
            for (int i = 0; i < TM; ++i)
#pragma unroll
                for (int j = 0; j < TN; ++j)
                    acc[i][j] = fmaf(ra[i], rb[j], acc[i][j]);
        }
        __syncthreads();
    }

#pragma unroll
    for (int i = 0; i < TM; ++i) {
        int m = mBase + ty + i;
        if (m < NN) {
            float* Cr = g_h + (size_t)m * DD + bx * BN + tx;
            *(float4*)(Cr)     = make_float4(acc[i][0], acc[i][1], acc[i][2], acc[i][3]);
            *(float4*)(Cr + 4) = make_float4(acc[i][4], acc[i][5], acc[i][6], acc[i][7]);
        }
    }
}

// ---------------- kernel 7: gather aggregation (atomic-free) ----------------
__global__ __launch_bounds__(128)
void agg_kernel(const int* __restrict__ eidx,
                const float* __restrict__ ew,
                const float* __restrict__ bias,
                float* __restrict__ out) {
    const int i = blockIdx.x;            // target node
    const int t = threadIdx.x;           // 0..127, owns 4 floats
    const float4* hb = (const float4*)g_h;

    const float di = g_dinv[i];
    float4 acc = ((const float4*)bias)[t];

    // self loop: norm = di * 1.0 * di
    {
        float sn = di * di;
        float4 hv = hb[(size_t)i * DV4 + t];
        acc.x += hv.x * sn; acc.y += hv.y * sn;
        acc.z += hv.z * sn; acc.w += hv.w * sn;
    }

    const int s = g_offsets[i];
    const int e_end = g_offsets[i + 1];
    for (int k = s; k < e_end; ++k) {
        int e = g_esorted[k];
        int r = eidx[e];                            // row (source)
        float nrm = g_dinv[r] * ew[e] * di;
        float4 v = hb[(size_t)r * DV4 + t];
        acc.x += v.x * nrm; acc.y += v.y * nrm;
        acc.z += v.z * nrm; acc.w += v.w * nrm;
    }

    ((float4*)out)[(size_t)i * DV4 + t] = acc;
}

// ---------------- launcher ----------------
extern "C" void kernel_launch(void* const* d_in, const int* in_sizes, int n_in,
                              void* d_out, int out_size) {
    const float* x    = (const float*)d_in[0];       // [NN, DD]
    const int*   eidx = (const int*)d_in[1];         // [2, EE] (int32 — JAX x64 disabled)
    const float* ea   = (const float*)d_in[2];       // [EE]
    const float* W    = (const float*)d_in[3];       // [DD, DD]
    const float* b    = (const float*)d_in[4];       // [DD]
    float*       out  = (float*)d_out;               // [NN, DD]

    init_kernel<<<(NN + 255) / 256, 256>>>();
    deg_kernel<<<(EE + 255) / 256, 256>>>(eidx, ea);
    dinv_kernel<<<(NN + 255) / 256, 256>>>();
    scan_kernel<<<1, 1024>>>();
    fill_kernel<<<(EE + 255) / 256, 256>>>(eidx);

    dim3 ggrid(DD / BN, (NN + BM - 1) / BM);
    sgemm_kernel<<<ggrid, 256>>>(x, W);

    agg_kernel<<<NN, 128>>>(eidx, ea, b, out);
}

// round 4
// speedup vs baseline: 1.7993x; 1.7993x over previous
#include <cuda_runtime.h>
#include <cuda_bf16.h>
#include <stdint.h>

// Problem constants
#define NN 10000          // nodes
#define EE 160000         // edges
#define DD 512            // feature dim (in == out)
#define DV4 (DD/4)        // 128 float4 per row

// ---------------- device scratch (no allocs allowed) ----------------
__device__ float g_dinv[NN];
__device__ int   g_counts[NN];
__device__ int   g_offsets[NN + 1];
__device__ int   g_cursor[NN];
__device__ int   g_esorted[EE];
__device__ float g_h[(size_t)NN * DD];            // h = x @ W (fp32, 20.5 MB)
__device__ __nv_bfloat16 g_xh[(size_t)NN * DD];   // x hi split
__device__ __nv_bfloat16 g_xl[(size_t)NN * DD];   // x lo split
__device__ __nv_bfloat16 g_wth[(size_t)DD * DD];  // W^T hi: [n][k]
__device__ __nv_bfloat16 g_wtl[(size_t)DD * DD];  // W^T lo

// =================== helpers ===================
__device__ __forceinline__ uint32_t smem_to_u32(const void* p) {
    uint32_t a;
    asm("{ .reg .u64 t; cvta.to.shared.u64 t, %1; cvt.u32.u64 %0, t; }"
        : "=r"(a) : "l"(p));
    return a;
}
// XOR swizzle for 128B rows: byte_off ^ ((row&7)<<4)
#define SWZ(o) ((o) ^ (((o) >> 3) & 0x70))

__device__ __forceinline__ void ldsm_x4(uint32_t r[4], uint32_t addr) {
    asm volatile("ldmatrix.sync.aligned.m8n8.x4.shared.b16 {%0,%1,%2,%3}, [%4];"
                 : "=r"(r[0]), "=r"(r[1]), "=r"(r[2]), "=r"(r[3]) : "r"(addr));
}
__device__ __forceinline__ void mma16816(float c[4], const uint32_t a[4],
                                         uint32_t b0, uint32_t b1) {
    asm volatile(
        "mma.sync.aligned.m16n8k16.row.col.f32.bf16.bf16.f32 "
        "{%0,%1,%2,%3}, {%4,%5,%6,%7}, {%8,%9}, {%0,%1,%2,%3};"
        : "+f"(c[0]), "+f"(c[1]), "+f"(c[2]), "+f"(c[3])
        : "r"(a[0]), "r"(a[1]), "r"(a[2]), "r"(a[3]), "r"(b0), "r"(b1));
}

// =================== kernel: split x into bf16 hi/lo ===================
__global__ void convx_kernel(const float* __restrict__ x) {
    size_t i = (size_t)blockIdx.x * 256 + threadIdx.x;   // float4 index
    if (i >= (size_t)NN * DD / 4) return;
    float4 v = ((const float4*)x)[i];
    __nv_bfloat16 h0 = __float2bfloat16(v.x);
    __nv_bfloat16 h1 = __float2bfloat16(v.y);
    __nv_bfloat16 h2 = __float2bfloat16(v.z);
    __nv_bfloat16 h3 = __float2bfloat16(v.w);
    __nv_bfloat16 l0 = __float2bfloat16(v.x - __bfloat162float(h0));
    __nv_bfloat16 l1 = __float2bfloat16(v.y - __bfloat162float(h1));
    __nv_bfloat16 l2 = __float2bfloat16(v.z - __bfloat162float(h2));
    __nv_bfloat16 l3 = __float2bfloat16(v.w - __bfloat162float(h3));
    __nv_bfloat162 ph0 = __halves2bfloat162(h0, h1);
    __nv_bfloat162 ph1 = __halves2bfloat162(h2, h3);
    __nv_bfloat162 pl0 = __halves2bfloat162(l0, l1);
    __nv_bfloat162 pl1 = __halves2bfloat162(l2, l3);
    uint2 ph, pl;
    ph.x = *(uint32_t*)&ph0; ph.y = *(uint32_t*)&ph1;
    pl.x = *(uint32_t*)&pl0; pl.y = *(uint32_t*)&pl1;
    ((uint2*)g_xh)[i] = ph;
    ((uint2*)g_xl)[i] = pl;
}

// =================== kernel: transpose+split W ===================
__global__ void convw_kernel(const float* __restrict__ W) {
    int n = blockIdx.x;                  // output col = W^T row
    for (int k = threadIdx.x; k < DD; k += 256) {
        float v = W[(size_t)k * DD + n];
        __nv_bfloat16 h = __float2bfloat16(v);
        __nv_bfloat16 l = __float2bfloat16(v - __bfloat162float(h));
        g_wth[(size_t)n * DD + k] = h;
        g_wtl[(size_t)n * DD + k] = l;
    }
}

// =================== CSR-build kernels ===================
__global__ void init_kernel() {
    int i = blockIdx.x * blockDim.x + threadIdx.x;
    if (i < NN) { g_dinv[i] = 1.0f; g_counts[i] = 0; }
}

__global__ void deg_kernel(const int* __restrict__ eidx,
                           const float* __restrict__ ew) {
    int e = blockIdx.x * blockDim.x + threadIdx.x;
    if (e < EE) {
        int c = eidx[EE + e];
        atomicAdd(&g_dinv[c], ew[e]);
        atomicAdd(&g_counts[c], 1);
    }
}

// scan (warp-shuffle) + dinv finalize, 1 block of 1024
__global__ void scan_kernel() {
    __shared__ int warpsum[32];
    const int CH = (NN + 1023) / 1024;   // 10
    int t = threadIdx.x;
    int lane = t & 31, w = t >> 5;
    int base = t * CH;
    int local[CH];
    int sum = 0;
#pragma unroll
    for (int i = 0; i < CH; ++i) {
        int idx = base + i;
        local[i] = (idx < NN) ? g_counts[idx] : 0;
        sum += local[i];
        if (idx < NN) g_dinv[idx] = rsqrtf(g_dinv[idx]);
    }
    int v = sum;
#pragma unroll
    for (int o = 1; o < 32; o <<= 1) {
        int u = __shfl_up_sync(0xFFFFFFFFu, v, o);
        if (lane >= o) v += u;
    }
    if (lane == 31) warpsum[w] = v;
    __syncthreads();
    if (w == 0) {
        int s = warpsum[lane];
#pragma unroll
        for (int o = 1; o < 32; o <<= 1) {
            int u = __shfl_up_sync(0xFFFFFFFFu, s, o);
            if (lane >= o) s += u;
        }
        warpsum[lane] = s;
    }
    __syncthreads();
    int run = v - sum + (w ? warpsum[w - 1] : 0);
#pragma unroll
    for (int i = 0; i < CH; ++i) {
        int idx = base + i;
        if (idx < NN) {
            g_offsets[idx] = run;
            g_cursor[idx]  = run;
            run += local[i];
        }
    }
    if (t == 1023) g_offsets[NN] = warpsum[31];
}

__global__ void fill_kernel(const int* __restrict__ eidx) {
    int e = blockIdx.x * blockDim.x + threadIdx.x;
    if (e < EE) {
        int c = eidx[EE + e];
        int p = atomicAdd(&g_cursor[c], 1);
        g_esorted[p] = e;
    }
}

// =================== mma.sync GEMM: g_h = x @ W ===================
// CTA tile 128(M) x 128(N), K-chunk 64. 8 warps, each 64x32.
// 3 split-term mmas (hi*hi + hi*lo + lo*hi) into fp32.
#define SA_HI 0
#define SA_LO 16384
#define SB_HI 32768
#define SB_LO 49152
#define GEMM_SMEM 65536

__global__ void __launch_bounds__(256, 2)
gemm_kernel() {
    extern __shared__ char smem[];
    const uint32_t sb = smem_to_u32(smem);
    const int tid  = threadIdx.x;
    const int wid  = tid >> 5;
    const int lane = tid & 31;
    const int wy   = wid >> 2;            // 0..1  (M)
    const int wx   = wid & 3;             // 0..3  (N)
    const int mBase = blockIdx.y * 128;
    const int nBase = blockIdx.x * 128;

    float c[4][4][4];                      // [mt][nt][reg]
#pragma unroll
    for (int i = 0; i < 4; ++i)
#pragma unroll
        for (int j = 0; j < 4; ++j)
#pragma unroll
            for (int r = 0; r < 4; ++r) c[i][j][r] = 0.0f;

    // per-lane ldmatrix base offsets (within a 16KB region, before k-step)
    // A: row = wy*64 + mt*16 + (lane&15), kunit = kb + (lane>>4)
    const int aRow = wy * 64 + (lane & 15);
    const int aKu  = (lane >> 4);
    // B: n = wx*32 + pair*16 + (lane&7) + ((lane>>4)&1)*8, kunit = kb + ((lane>>3)&1)
    const int bRow = wx * 32 + (lane & 7) + ((lane >> 4) & 1) * 8;
    const int bKu  = ((lane >> 3) & 1);

    for (int kc = 0; kc < DD; kc += 64) {
        // ---- cooperative loads: 4096 uint4, 16 per thread ----
#pragma unroll
        for (int it = 0; it < 16; ++it) {
            int vv = tid + it * 256;
            int v0 = vv & 1023;
            int row = v0 >> 3, g = v0 & 7;
            const __nv_bfloat16* srcp;
            int region;
            size_t srcRow;
            if (vv < 2048) {
                int m = mBase + row; if (m > NN - 1) m = NN - 1;
                srcp = (vv < 1024) ? g_xh : g_xl;
                region = (vv < 1024) ? SA_HI : SA_LO;
                srcRow = (size_t)m;
            } else {
                srcp = (vv < 3072) ? g_wth : g_wtl;
                region = (vv < 3072) ? SB_HI : SB_LO;
                srcRow = (size_t)(nBase + row);
            }
            uint4 val = *(const uint4*)(srcp + srcRow * DD + kc + g * 8);
            *(uint4*)(smem + region + SWZ(row * 128 + g * 16)) = val;
        }
        __syncthreads();

        // ---- compute 4 k16 steps ----
#pragma unroll
        for (int k16 = 0; k16 < 4; ++k16) {
            const int kb = k16 * 2;
            uint32_t a[4][4], bh[2][4], bl[2][4];
#pragma unroll
            for (int mt = 0; mt < 4; ++mt) {
                int off = SWZ((aRow + mt * 16) * 128 + (kb + aKu) * 16);
                ldsm_x4(a[mt], sb + SA_HI + off);
            }
#pragma unroll
            for (int pr = 0; pr < 2; ++pr) {
                int off = SWZ((bRow + pr * 16) * 128 + (kb + bKu) * 16);
                ldsm_x4(bh[pr], sb + SB_HI + off);
                ldsm_x4(bl[pr], sb + SB_LO + off);
            }
            // hi*hi
#pragma unroll
            for (int mt = 0; mt < 4; ++mt)
#pragma unroll
                for (int nt = 0; nt < 4; ++nt)
                    mma16816(c[mt][nt], a[mt], bh[nt >> 1][(nt & 1) * 2],
                             bh[nt >> 1][(nt & 1) * 2 + 1]);
            // hi*lo
#pragma unroll
            for (int mt = 0; mt < 4; ++mt)
#pragma unroll
                for (int nt = 0; nt < 4; ++nt)
                    mma16816(c[mt][nt], a[mt], bl[nt >> 1][(nt & 1) * 2],
                             bl[nt >> 1][(nt & 1) * 2 + 1]);
            // lo*hi: reload a with lo split
#pragma unroll
            for (int mt = 0; mt < 4; ++mt) {
                int off = SWZ((aRow + mt * 16) * 128 + (kb + aKu) * 16);
                ldsm_x4(a[mt], sb + SA_LO + off);
            }
#pragma unroll
            for (int mt = 0; mt < 4; ++mt)
#pragma unroll
                for (int nt = 0; nt < 4; ++nt)
                    mma16816(c[mt][nt], a[mt], bh[nt >> 1][(nt & 1) * 2],
                             bh[nt >> 1][(nt & 1) * 2 + 1]);
        }
        __syncthreads();
    }

    // ---- epilogue: direct v2 stores to g_h ----
    const int erow = mBase + wy * 64 + (lane >> 2);
    const int ecol = nBase + wx * 32 + (lane & 3) * 2;
#pragma unroll
    for (int mt = 0; mt < 4; ++mt) {
#pragma unroll
        for (int nt = 0; nt < 4; ++nt) {
            int r0 = erow + mt * 16;
            int cc = ecol + nt * 8;
            if (r0 < NN)
                *(float2*)&g_h[(size_t)r0 * DD + cc] =
                    make_float2(c[mt][nt][0], c[mt][nt][1]);
            if (r0 + 8 < NN)
                *(float2*)&g_h[(size_t)(r0 + 8) * DD + cc] =
                    make_float2(c[mt][nt][2], c[mt][nt][3]);
        }
    }
}

// =================== aggregation (atomic-free gather) ===================
__global__ __launch_bounds__(128)
void agg_kernel(const int* __restrict__ eidx,
                const float* __restrict__ ew,
                const float* __restrict__ bias,
                float* __restrict__ out) {
    const int i = blockIdx.x;
    const int t = threadIdx.x;
    const float4* hb = (const float4*)g_h;

    const float di = g_dinv[i];
    float4 acc = ((const float4*)bias)[t];
    {
        float sn = di * di;
        float4 hv = hb[(size_t)i * DV4 + t];
        acc.x += hv.x * sn; acc.y += hv.y * sn;
        acc.z += hv.z * sn; acc.w += hv.w * sn;
    }
    const int s = g_offsets[i];
    const int e_end = g_offsets[i + 1];
    for (int k = s; k < e_end; ++k) {
        int e = g_esorted[k];
        int r = eidx[e];
        float nrm = g_dinv[r] * ew[e] * di;
        float4 v = hb[(size_t)r * DV4 + t];
        acc.x += v.x * nrm; acc.y += v.y * nrm;
        acc.z += v.z * nrm; acc.w += v.w * nrm;
    }
    ((float4*)out)[(size_t)i * DV4 + t] = acc;
}

// =================== launcher ===================
extern "C" void kernel_launch(void* const* d_in, const int* in_sizes, int n_in,
                              void* d_out, int out_size) {
    const float* x    = (const float*)d_in[0];       // [NN, DD]
    const int*   eidx = (const int*)d_in[1];         // [2, EE] int32
    const float* ea   = (const float*)d_in[2];       // [EE]
    const float* W    = (const float*)d_in[3];       // [DD, DD]
    const float* b    = (const float*)d_in[4];       // [DD]
    float*       out  = (float*)d_out;               // [NN, DD]

    cudaFuncSetAttribute(gemm_kernel,
                         cudaFuncAttributeMaxDynamicSharedMemorySize, GEMM_SMEM);

    convx_kernel<<<(NN * DD / 4 + 255) / 256, 256>>>(x);
    convw_kernel<<<DD, 256>>>(W);

    init_kernel<<<(NN + 255) / 256, 256>>>();
    deg_kernel<<<(EE + 255) / 256, 256>>>(eidx, ea);
    scan_kernel<<<1, 1024>>>();
    fill_kernel<<<(EE + 255) / 256, 256>>>(eidx);

    dim3 ggrid(DD / 128, (NN + 127) / 128);          // (4, 79)
    gemm_kernel<<<ggrid, 256, GEMM_SMEM>>>();

    agg_kernel<<<NN, 128>>>(eidx, ea, b, out);
}

// round 5
// speedup vs baseline: 2.6475x; 1.4714x over previous
#include <cuda_runtime.h>
#include <cuda_bf16.h>
#include <stdint.h>

// Problem constants
#define NN 10000          // nodes
#define EE 160000         // edges
#define DD 512            // feature dim (in == out)
#define DV4 (DD/4)        // 128 float4 per row

// ---------------- device scratch (no allocs allowed) ----------------
__device__ float g_dinv[NN];
__device__ int   g_counts[NN];
__device__ int   g_offsets[NN + 1];
__device__ int   g_cursor[NN];
__device__ int   g_esrc[EE];                      // per-slot source node
__device__ float g_enorm[EE];                     // per-slot norm coeff
__device__ float g_h[(size_t)NN * DD];            // h = x @ W (fp32, 20.5 MB)
__device__ __nv_bfloat16 g_xh[(size_t)NN * DD];   // x hi split
__device__ __nv_bfloat16 g_xl[(size_t)NN * DD];   // x lo split
__device__ __nv_bfloat16 g_wth[(size_t)DD * DD];  // W^T hi: [n][k]
__device__ __nv_bfloat16 g_wtl[(size_t)DD * DD];  // W^T lo

// =================== helpers ===================
__device__ __forceinline__ uint32_t smem_to_u32(const void* p) {
    uint32_t a;
    asm("{ .reg .u64 t; cvta.to.shared.u64 t, %1; cvt.u32.u64 %0, t; }"
        : "=r"(a) : "l"(p));
    return a;
}
// XOR swizzle for 64B rows
#define SWZ64(o) ((o) ^ (((o) >> 3) & 0x30))

__device__ __forceinline__ void ldsm_x4(uint32_t r[4], uint32_t addr) {
    asm volatile("ldmatrix.sync.aligned.m8n8.x4.shared.b16 {%0,%1,%2,%3}, [%4];"
                 : "=r"(r[0]), "=r"(r[1]), "=r"(r[2]), "=r"(r[3]) : "r"(addr));
}
__device__ __forceinline__ void mma16816(float c[4], const uint32_t a[4],
                                         uint32_t b0, uint32_t b1) {
    asm volatile(
        "mma.sync.aligned.m16n8k16.row.col.f32.bf16.bf16.f32 "
        "{%0,%1,%2,%3}, {%4,%5,%6,%7}, {%8,%9}, {%0,%1,%2,%3};"
        : "+f"(c[0]), "+f"(c[1]), "+f"(c[2]), "+f"(c[3])
        : "r"(a[0]), "r"(a[1]), "r"(a[2]), "r"(a[3]), "r"(b0), "r"(b1));
}
__device__ __forceinline__ void cp16(uint32_t dst, const void* src) {
    asm volatile("cp.async.cg.shared.global [%0], [%1], 16;"
                 :: "r"(dst), "l"(src));
}
#define CP_COMMIT() asm volatile("cp.async.commit_group;" ::: "memory")
#define CP_WAIT1()  asm volatile("cp.async.wait_group 1;" ::: "memory")
#define CP_WAIT0()  asm volatile("cp.async.wait_group 0;" ::: "memory")

// =================== fused prep: split x, transpose+split W, init ===================
// blocks [0,5000): x split; [5000,5512): W cols; [5512,5552): init
__global__ void prep_kernel(const float* __restrict__ x,
                            const float* __restrict__ W) {
    const int bid = blockIdx.x;
    if (bid < 5000) {
        size_t i = (size_t)bid * 256 + threadIdx.x;   // float4 index
        float4 v = ((const float4*)x)[i];
        __nv_bfloat16 h0 = __float2bfloat16(v.x);
        __nv_bfloat16 h1 = __float2bfloat16(v.y);
        __nv_bfloat16 h2 = __float2bfloat16(v.z);
        __nv_bfloat16 h3 = __float2bfloat16(v.w);
        __nv_bfloat16 l0 = __float2bfloat16(v.x - __bfloat162float(h0));
        __nv_bfloat16 l1 = __float2bfloat16(v.y - __bfloat162float(h1));
        __nv_bfloat16 l2 = __float2bfloat16(v.z - __bfloat162float(h2));
        __nv_bfloat16 l3 = __float2bfloat16(v.w - __bfloat162float(h3));
        __nv_bfloat162 ph0 = __halves2bfloat162(h0, h1);
        __nv_bfloat162 ph1 = __halves2bfloat162(h2, h3);
        __nv_bfloat162 pl0 = __halves2bfloat162(l0, l1);
        __nv_bfloat162 pl1 = __halves2bfloat162(l2, l3);
        uint2 ph, pl;
        ph.x = *(uint32_t*)&ph0; ph.y = *(uint32_t*)&ph1;
        pl.x = *(uint32_t*)&pl0; pl.y = *(uint32_t*)&pl1;
        ((uint2*)g_xh)[i] = ph;
        ((uint2*)g_xl)[i] = pl;
    } else if (bid < 5512) {
        int n = bid - 5000;
        for (int k = threadIdx.x; k < DD; k += 256) {
            float v = W[(size_t)k * DD + n];
            __nv_bfloat16 h = __float2bfloat16(v);
            __nv_bfloat16 l = __float2bfloat16(v - __bfloat162float(h));
            g_wth[(size_t)n * DD + k] = h;
            g_wtl[(size_t)n * DD + k] = l;
        }
    } else {
        int i = (bid - 5512) * 256 + threadIdx.x;
        if (i < NN) { g_dinv[i] = 1.0f; g_counts[i] = 0; }
    }
}

// =================== CSR-build kernels ===================
__global__ void deg_kernel(const int* __restrict__ eidx,
                           const float* __restrict__ ew) {
    int e = blockIdx.x * blockDim.x + threadIdx.x;
    if (e < EE) {
        int c = eidx[EE + e];
        atomicAdd(&g_dinv[c], ew[e]);
        atomicAdd(&g_counts[c], 1);
    }
}

// scan (warp-shuffle) + dinv finalize, 1 block of 1024
__global__ void scan_kernel() {
    __shared__ int warpsum[32];
    const int CH = (NN + 1023) / 1024;   // 10
    int t = threadIdx.x;
    int lane = t & 31, w = t >> 5;
    int base = t * CH;
    int local[CH];
    int sum = 0;
#pragma unroll
    for (int i = 0; i < CH; ++i) {
        int idx = base + i;
        local[i] = (idx < NN) ? g_counts[idx] : 0;
        sum += local[i];
        if (idx < NN) g_dinv[idx] = rsqrtf(g_dinv[idx]);
    }
    int v = sum;
#pragma unroll
    for (int o = 1; o < 32; o <<= 1) {
        int u = __shfl_up_sync(0xFFFFFFFFu, v, o);
        if (lane >= o) v += u;
    }
    if (lane == 31) warpsum[w] = v;
    __syncthreads();
    if (w == 0) {
        int s = warpsum[lane];
#pragma unroll
        for (int o = 1; o < 32; o <<= 1) {
            int u = __shfl_up_sync(0xFFFFFFFFu, s, o);
            if (lane >= o) s += u;
        }
        warpsum[lane] = s;
    }
    __syncthreads();
    int run = v - sum + (w ? warpsum[w - 1] : 0);
#pragma unroll
    for (int i = 0; i < CH; ++i) {
        int idx = base + i;
        if (idx < NN) {
            g_offsets[idx] = run;
            g_cursor[idx]  = run;
            run += local[i];
        }
    }
    if (t == 1023) g_offsets[NN] = warpsum[31];
}

// fill: resolve (src, norm) per slot (dinv is final here)
__global__ void fill_kernel(const int* __restrict__ eidx,
                            const float* __restrict__ ew) {
    int e = blockIdx.x * blockDim.x + threadIdx.x;
    if (e < EE) {
        int c = eidx[EE + e];
        int r = eidx[e];
        float nrm = g_dinv[r] * ew[e] * g_dinv[c];
        int p = atomicAdd(&g_cursor[c], 1);
        g_esrc[p]  = r;
        g_enorm[p] = nrm;
    }
}

// =================== mma.sync GEMM: g_h = x @ W ===================
// CTA tile 128(M) x 128(N), K-chunk 32, 2-stage cp.async pipeline.
// Stage layout (32KB): A_HI 0 | A_LO 8K | B_HI 16K | B_LO 24K ; 64B rows, SW64.
#define KC 32
#define NCH (DD / KC)            // 16
#define STAGE 32768
#define GEMM_SMEM (2 * STAGE)    // 65536

__device__ __forceinline__ void gemm_load_stage(uint32_t sb, int stOff, int kc,
                                                int tid, int mBase, int nBase) {
    const int kOff = kc * KC;
#pragma unroll
    for (int it = 0; it < 8; ++it) {
        int vv = tid + it * 256;            // 0..2047
        int row = (vv & 511) >> 2;          // 0..127
        int g   = vv & 3;                   // 16B unit
        const __nv_bfloat16* srcp;
        int region;
        size_t srcRow;
        if (vv < 1024) {
            int m = mBase + row; if (m > NN - 1) m = NN - 1;
            srcp = (vv < 512) ? g_xh : g_xl;
            region = (vv < 512) ? 0 : 8192;
            srcRow = (size_t)m;
        } else {
            srcp = (vv < 1536) ? g_wth : g_wtl;
            region = (vv < 1536) ? 16384 : 24576;
            srcRow = (size_t)(nBase + row);
        }
        cp16(sb + stOff + region + SWZ64(row * 64 + g * 16),
             srcp + srcRow * DD + kOff + g * 8);
    }
}

__global__ void __launch_bounds__(256, 2)
gemm_kernel() {
    extern __shared__ char smem[];
    const uint32_t sb = smem_to_u32(smem);
    const int tid  = threadIdx.x;
    const int wid  = tid >> 5;
    const int lane = tid & 31;
    const int wy   = wid >> 2;            // 0..1  (M)
    const int wx   = wid & 3;             // 0..3  (N)
    const int mBase = blockIdx.y * 128;
    const int nBase = blockIdx.x * 128;

    float c[4][4][4];
#pragma unroll
    for (int i = 0; i < 4; ++i)
#pragma unroll
        for (int j = 0; j < 4; ++j)
#pragma unroll
            for (int r = 0; r < 4; ++r) c[i][j][r] = 0.0f;

    const int aRow = wy * 64 + (lane & 15);
    const int aKu  = (lane >> 4);
    const int bRow = wx * 32 + (lane & 7) + ((lane >> 4) & 1) * 8;
    const int bKu  = ((lane >> 3) & 1);

    gemm_load_stage(sb, 0, 0, tid, mBase, nBase);
    CP_COMMIT();

    for (int kc = 0; kc < NCH; ++kc) {
        const int stOff = (kc & 1) * STAGE;
        if (kc + 1 < NCH) {
            gemm_load_stage(sb, ((kc + 1) & 1) * STAGE, kc + 1, tid, mBase, nBase);
            CP_COMMIT();
            CP_WAIT1();
        } else {
            CP_WAIT0();
        }
        __syncthreads();

#pragma unroll
        for (int k16 = 0; k16 < 2; ++k16) {
            const int kb = k16 * 2;
            uint32_t a[4][4], bh[2][4], bl[2][4];
#pragma unroll
            for (int mt = 0; mt < 4; ++mt) {
                int off = SWZ64((aRow + mt * 16) * 64 + (kb + aKu) * 16);
                ldsm_x4(a[mt], sb + stOff + 0 + off);
            }
#pragma unroll
            for (int pr = 0; pr < 2; ++pr) {
                int off = SWZ64((bRow + pr * 16) * 64 + (kb + bKu) * 16);
                ldsm_x4(bh[pr], sb + stOff + 16384 + off);
                ldsm_x4(bl[pr], sb + stOff + 24576 + off);
            }
            // hi*hi
#pragma unroll
            for (int mt = 0; mt < 4; ++mt)
#pragma unroll
                for (int nt = 0; nt < 4; ++nt)
                    mma16816(c[mt][nt], a[mt], bh[nt >> 1][(nt & 1) * 2],
                             bh[nt >> 1][(nt & 1) * 2 + 1]);
            // hi*lo
#pragma unroll
            for (int mt = 0; mt < 4; ++mt)
#pragma unroll
                for (int nt = 0; nt < 4; ++nt)
                    mma16816(c[mt][nt], a[mt], bl[nt >> 1][(nt & 1) * 2],
                             bl[nt >> 1][(nt & 1) * 2 + 1]);
            // lo*hi
#pragma unroll
            for (int mt = 0; mt < 4; ++mt) {
                int off = SWZ64((aRow + mt * 16) * 64 + (kb + aKu) * 16);
                ldsm_x4(a[mt], sb + stOff + 8192 + off);
            }
#pragma unroll
            for (int mt = 0; mt < 4; ++mt)
#pragma unroll
                for (int nt = 0; nt < 4; ++nt)
                    mma16816(c[mt][nt], a[mt], bh[nt >> 1][(nt & 1) * 2],
                             bh[nt >> 1][(nt & 1) * 2 + 1]);
        }
        __syncthreads();
    }

    // epilogue: direct v2 stores to g_h
    const int erow = mBase + wy * 64 + (lane >> 2);
    const int ecol = nBase + wx * 32 + (lane & 3) * 2;
#pragma unroll
    for (int mt = 0; mt < 4; ++mt) {
#pragma unroll
        for (int nt = 0; nt < 4; ++nt) {
            int r0 = erow + mt * 16;
            int cc = ecol + nt * 8;
            if (r0 < NN)
                *(float2*)&g_h[(size_t)r0 * DD + cc] =
                    make_float2(c[mt][nt][0], c[mt][nt][1]);
            if (r0 + 8 < NN)
                *(float2*)&g_h[(size_t)(r0 + 8) * DD + cc] =
                    make_float2(c[mt][nt][2], c[mt][nt][3]);
        }
    }
}

// =================== aggregation (atomic-free gather, unrolled) ===================
__global__ __launch_bounds__(128)
void agg_kernel(const float* __restrict__ bias,
                float* __restrict__ out) {
    const int i = blockIdx.x;
    const int t = threadIdx.x;
    const float4* hb = (const float4*)g_h;

    const float di = g_dinv[i];
    float4 acc = ((const float4*)bias)[t];
    {
        float sn = di * di;
        float4 hv = hb[(size_t)i * DV4 + t];
        acc.x += hv.x * sn; acc.y += hv.y * sn;
        acc.z += hv.z * sn; acc.w += hv.w * sn;
    }
    int k = g_offsets[i];
    const int kend = g_offsets[i + 1];
    for (; k + 1 < kend; k += 2) {
        int r0 = g_esrc[k];
        int r1 = g_esrc[k + 1];
        float n0 = g_enorm[k];
        float n1 = g_enorm[k + 1];
        float4 v0 = hb[(size_t)r0 * DV4 + t];
        float4 v1 = hb[(size_t)r1 * DV4 + t];
        acc.x += v0.x * n0 + v1.x * n1;
        acc.y += v0.y * n0 + v1.y * n1;
        acc.z += v0.z * n0 + v1.z * n1;
        acc.w += v0.w * n0 + v1.w * n1;
    }
    if (k < kend) {
        int r0 = g_esrc[k];
        float n0 = g_enorm[k];
        float4 v0 = hb[(size_t)r0 * DV4 + t];
        acc.x += v0.x * n0; acc.y += v0.y * n0;
        acc.z += v0.z * n0; acc.w += v0.w * n0;
    }
    ((float4*)out)[(size_t)i * DV4 + t] = acc;
}

// =================== launcher (fork-join: CSR chain overlaps GEMM) ===================
extern "C" void kernel_launch(void* const* d_in, const int* in_sizes, int n_in,
                              void* d_out, int out_size) {
    const float* x    = (const float*)d_in[0];       // [NN, DD]
    const int*   eidx = (const int*)d_in[1];         // [2, EE] int32
    const float* ea   = (const float*)d_in[2];       // [EE]
    const float* W    = (const float*)d_in[3];       // [DD, DD]
    const float* b    = (const float*)d_in[4];       // [DD]
    float*       out  = (float*)d_out;               // [NN, DD]

    static cudaStream_t s2 = nullptr;
    static cudaEvent_t evFork = nullptr, evJoin = nullptr;
    if (s2 == nullptr) {
        cudaStreamCreateWithFlags(&s2, cudaStreamNonBlocking);
        cudaEventCreateWithFlags(&evFork, cudaEventDisableTiming);
        cudaEventCreateWithFlags(&evJoin, cudaEventDisableTiming);
        cudaFuncSetAttribute(gemm_kernel,
                             cudaFuncAttributeMaxDynamicSharedMemorySize, GEMM_SMEM);
    }

    // prep: x split + W^T split + init (5552 blocks)
    prep_kernel<<<5552, 256>>>(x, W);

    // fork CSR chain onto s2
    cudaEventRecord(evFork, 0);
    cudaStreamWaitEvent(s2, evFork, 0);
    deg_kernel<<<(EE + 255) / 256, 256, 0, s2>>>(eidx, ea);
    scan_kernel<<<1, 1024, 0, s2>>>();
    fill_kernel<<<(EE + 255) / 256, 256, 0, s2>>>(eidx, ea);
    cudaEventRecord(evJoin, s2);

    // GEMM on main stream (overlaps CSR chain)
    dim3 ggrid(DD / 128, (NN + 127) / 128);          // (4, 79)
    gemm_kernel<<<ggrid, 256, GEMM_SMEM>>>();

    // join, then aggregate
    cudaStreamWaitEvent(0, evJoin, 0);
    agg_kernel<<<NN, 128>>>(b, out);
}

// round 6
// speedup vs baseline: 2.8112x; 1.0618x over previous
#include <cuda_runtime.h>
#include <cuda_bf16.h>
#include <cuda_fp16.h>
#include <stdint.h>

// Problem constants
#define NN 10000          // nodes
#define EE 160000         // edges
#define DD 512            // feature dim (in == out)
#define DV8 (DD/8)        // 64 uint4-of-half per row

// ---------------- device scratch (no allocs allowed) ----------------
__device__ float g_dinv[NN];
__device__ int   g_counts[NN];
__device__ int   g_offsets[NN + 1];
__device__ int   g_cursor[NN];
__device__ int   g_esrc[EE];                      // per-slot source node
__device__ float g_enorm[EE];                     // per-slot norm coeff
__device__ __half g_h[(size_t)NN * DD];           // h = x @ W (fp16, 10.2 MB)
__device__ __nv_bfloat16 g_xh[(size_t)NN * DD];   // x hi split
__device__ __nv_bfloat16 g_xl[(size_t)NN * DD];   // x lo split
__device__ __nv_bfloat16 g_wth[(size_t)DD * DD];  // W^T hi: [n][k]
__device__ __nv_bfloat16 g_wtl[(size_t)DD * DD];  // W^T lo

// =================== helpers ===================
__device__ __forceinline__ uint32_t smem_to_u32(const void* p) {
    uint32_t a;
    asm("{ .reg .u64 t; cvta.to.shared.u64 t, %1; cvt.u32.u64 %0, t; }"
        : "=r"(a) : "l"(p));
    return a;
}
// XOR swizzle for 64B rows
#define SWZ64(o) ((o) ^ (((o) >> 3) & 0x30))

__device__ __forceinline__ void ldsm_x4(uint32_t r[4], uint32_t addr) {
    asm volatile("ldmatrix.sync.aligned.m8n8.x4.shared.b16 {%0,%1,%2,%3}, [%4];"
                 : "=r"(r[0]), "=r"(r[1]), "=r"(r[2]), "=r"(r[3]) : "r"(addr));
}
__device__ __forceinline__ void mma16816(float c[4], const uint32_t a[4],
                                         uint32_t b0, uint32_t b1) {
    asm volatile(
        "mma.sync.aligned.m16n8k16.row.col.f32.bf16.bf16.f32 "
        "{%0,%1,%2,%3}, {%4,%5,%6,%7}, {%8,%9}, {%0,%1,%2,%3};"
        : "+f"(c[0]), "+f"(c[1]), "+f"(c[2]), "+f"(c[3])
        : "r"(a[0]), "r"(a[1]), "r"(a[2]), "r"(a[3]), "r"(b0), "r"(b1));
}
__device__ __forceinline__ void cp16(uint32_t dst, const void* src) {
    asm volatile("cp.async.cg.shared.global [%0], [%1], 16;"
                 :: "r"(dst), "l"(src));
}
#define CP_COMMIT() asm volatile("cp.async.commit_group;" ::: "memory")
#define CP_WAIT1()  asm volatile("cp.async.wait_group 1;" ::: "memory")
#define CP_WAIT0()  asm volatile("cp.async.wait_group 0;" ::: "memory")

// =================== prep: split x, transpose+split W ===================
// blocks [0,5000): x split; [5000,5512): W cols
__global__ void prep_kernel(const float* __restrict__ x,
                            const float* __restrict__ W) {
    const int bid = blockIdx.x;
    if (bid < 5000) {
        size_t i = (size_t)bid * 256 + threadIdx.x;   // float4 index
        float4 v = ((const float4*)x)[i];
        __nv_bfloat16 h0 = __float2bfloat16(v.x);
        __nv_bfloat16 h1 = __float2bfloat16(v.y);
        __nv_bfloat16 h2 = __float2bfloat16(v.z);
        __nv_bfloat16 h3 = __float2bfloat16(v.w);
        __nv_bfloat16 l0 = __float2bfloat16(v.x - __bfloat162float(h0));
        __nv_bfloat16 l1 = __float2bfloat16(v.y - __bfloat162float(h1));
        __nv_bfloat16 l2 = __float2bfloat16(v.z - __bfloat162float(h2));
        __nv_bfloat16 l3 = __float2bfloat16(v.w - __bfloat162float(h3));
        __nv_bfloat162 ph0 = __halves2bfloat162(h0, h1);
        __nv_bfloat162 ph1 = __halves2bfloat162(h2, h3);
        __nv_bfloat162 pl0 = __halves2bfloat162(l0, l1);
        __nv_bfloat162 pl1 = __halves2bfloat162(l2, l3);
        uint2 ph, pl;
        ph.x = *(uint32_t*)&ph0; ph.y = *(uint32_t*)&ph1;
        pl.x = *(uint32_t*)&pl0; pl.y = *(uint32_t*)&pl1;
        ((uint2*)g_xh)[i] = ph;
        ((uint2*)g_xl)[i] = pl;
    } else {
        int n = bid - 5000;
        for (int k = threadIdx.x; k < DD; k += 256) {
            float v = W[(size_t)k * DD + n];
            __nv_bfloat16 h = __float2bfloat16(v);
            __nv_bfloat16 l = __float2bfloat16(v - __bfloat162float(h));
            g_wth[(size_t)n * DD + k] = h;
            g_wtl[(size_t)n * DD + k] = l;
        }
    }
}

// =================== CSR-build kernels (stream 2) ===================
__global__ void init_kernel() {
    int i = blockIdx.x * blockDim.x + threadIdx.x;
    if (i < NN) { g_dinv[i] = 1.0f; g_counts[i] = 0; }
}

__global__ void deg_kernel(const int* __restrict__ eidx,
                           const float* __restrict__ ew) {
    int e = blockIdx.x * blockDim.x + threadIdx.x;
    if (e < EE) {
        int c = eidx[EE + e];
        atomicAdd(&g_dinv[c], ew[e]);
        atomicAdd(&g_counts[c], 1);
    }
}

// scan (warp-shuffle) + dinv finalize, 1 block of 1024
__global__ void scan_kernel() {
    __shared__ int warpsum[32];
    const int CH = (NN + 1023) / 1024;   // 10
    int t = threadIdx.x;
    int lane = t & 31, w = t >> 5;
    int base = t * CH;
    int local[CH];
    int sum = 0;
#pragma unroll
    for (int i = 0; i < CH; ++i) {
        int idx = base + i;
        local[i] = (idx < NN) ? g_counts[idx] : 0;
        sum += local[i];
        if (idx < NN) g_dinv[idx] = rsqrtf(g_dinv[idx]);
    }
    int v = sum;
#pragma unroll
    for (int o = 1; o < 32; o <<= 1) {
        int u = __shfl_up_sync(0xFFFFFFFFu, v, o);
        if (lane >= o) v += u;
    }
    if (lane == 31) warpsum[w] = v;
    __syncthreads();
    if (w == 0) {
        int s = warpsum[lane];
#pragma unroll
        for (int o = 1; o < 32; o <<= 1) {
            int u = __shfl_up_sync(0xFFFFFFFFu, s, o);
            if (lane >= o) s += u;
        }
        warpsum[lane] = s;
    }
    __syncthreads();
    int run = v - sum + (w ? warpsum[w - 1] : 0);
#pragma unroll
    for (int i = 0; i < CH; ++i) {
        int idx = base + i;
        if (idx < NN) {
            g_offsets[idx] = run;
            g_cursor[idx]  = run;
            run += local[i];
        }
    }
    if (t == 1023) g_offsets[NN] = warpsum[31];
}

// fill: resolve (src, norm) per slot (dinv is final here)
__global__ void fill_kernel(const int* __restrict__ eidx,
                            const float* __restrict__ ew) {
    int e = blockIdx.x * blockDim.x + threadIdx.x;
    if (e < EE) {
        int c = eidx[EE + e];
        int r = eidx[e];
        float nrm = g_dinv[r] * ew[e] * g_dinv[c];
        int p = atomicAdd(&g_cursor[c], 1);
        g_esrc[p]  = r;
        g_enorm[p] = nrm;
    }
}

// =================== mma.sync GEMM: g_h = x @ W (fp16 out) ===================
// CTA tile 128(M) x 128(N), K-chunk 32, 2-stage cp.async pipeline.
// Stage layout (32KB): A_HI 0 | A_LO 8K | B_HI 16K | B_LO 24K ; 64B rows, SW64.
#define KC 32
#define NCH (DD / KC)            // 16
#define STAGE 32768
#define GEMM_SMEM (2 * STAGE)    // 65536

__device__ __forceinline__ void gemm_load_stage(uint32_t sb, int stOff, int kc,
                                                int tid, int mBase, int nBase) {
    const int kOff = kc * KC;
#pragma unroll
    for (int it = 0; it < 8; ++it) {
        int vv = tid + it * 256;            // 0..2047
        int row = (vv & 511) >> 2;          // 0..127
        int g   = vv & 3;                   // 16B unit
        const __nv_bfloat16* srcp;
        int region;
        size_t srcRow;
        if (vv < 1024) {
            int m = mBase + row; if (m > NN - 1) m = NN - 1;
            srcp = (vv < 512) ? g_xh : g_xl;
            region = (vv < 512) ? 0 : 8192;
            srcRow = (size_t)m;
        } else {
            srcp = (vv < 1536) ? g_wth : g_wtl;
            region = (vv < 1536) ? 16384 : 24576;
            srcRow = (size_t)(nBase + row);
        }
        cp16(sb + stOff + region + SWZ64(row * 64 + g * 16),
             srcp + srcRow * DD + kOff + g * 8);
    }
}

__global__ void __launch_bounds__(256, 2)
gemm_kernel() {
    extern __shared__ char smem[];
    const uint32_t sb = smem_to_u32(smem);
    const int tid  = threadIdx.x;
    const int wid  = tid >> 5;
    const int lane = tid & 31;
    const int wy   = wid >> 2;            // 0..1  (M)
    const int wx   = wid & 3;             // 0..3  (N)
    const int mBase = blockIdx.y * 128;
    const int nBase = blockIdx.x * 128;

    float c[4][4][4];
#pragma unroll
    for (int i = 0; i < 4; ++i)
#pragma unroll
        for (int j = 0; j < 4; ++j)
#pragma unroll
            for (int r = 0; r < 4; ++r) c[i][j][r] = 0.0f;

    const int aRow = wy * 64 + (lane & 15);
    const int aKu  = (lane >> 4);
    const int bRow = wx * 32 + (lane & 7) + ((lane >> 4) & 1) * 8;
    const int bKu  = ((lane >> 3) & 1);

    gemm_load_stage(sb, 0, 0, tid, mBase, nBase);
    CP_COMMIT();

    for (int kc = 0; kc < NCH; ++kc) {
        const int stOff = (kc & 1) * STAGE;
        if (kc + 1 < NCH) {
            gemm_load_stage(sb, ((kc + 1) & 1) * STAGE, kc + 1, tid, mBase, nBase);
            CP_COMMIT();
            CP_WAIT1();
        } else {
            CP_WAIT0();
        }
        __syncthreads();

#pragma unroll
        for (int k16 = 0; k16 < 2; ++k16) {
            const int kb = k16 * 2;
            uint32_t a[4][4], bh[2][4], bl[2][4];
#pragma unroll
            for (int mt = 0; mt < 4; ++mt) {
                int off = SWZ64((aRow + mt * 16) * 64 + (kb + aKu) * 16);
                ldsm_x4(a[mt], sb + stOff + 0 + off);
            }
#pragma unroll
            for (int pr = 0; pr < 2; ++pr) {
                int off = SWZ64((bRow + pr * 16) * 64 + (kb + bKu) * 16);
                ldsm_x4(bh[pr], sb + stOff + 16384 + off);
                ldsm_x4(bl[pr], sb + stOff + 24576 + off);
            }
            // hi*hi
#pragma unroll
            for (int mt = 0; mt < 4; ++mt)
#pragma unroll
                for (int nt = 0; nt < 4; ++nt)
                    mma16816(c[mt][nt], a[mt], bh[nt >> 1][(nt & 1) * 2],
                             bh[nt >> 1][(nt & 1) * 2 + 1]);
            // hi*lo
#pragma unroll
            for (int mt = 0; mt < 4; ++mt)
#pragma unroll
                for (int nt = 0; nt < 4; ++nt)
                    mma16816(c[mt][nt], a[mt], bl[nt >> 1][(nt & 1) * 2],
                             bl[nt >> 1][(nt & 1) * 2 + 1]);
            // lo*hi
#pragma unroll
            for (int mt = 0; mt < 4; ++mt) {
                int off = SWZ64((aRow + mt * 16) * 64 + (kb + aKu) * 16);
                ldsm_x4(a[mt], sb + stOff + 8192 + off);
            }
#pragma unroll
            for (int mt = 0; mt < 4; ++mt)
#pragma unroll
                for (int nt = 0; nt < 4; ++nt)
                    mma16816(c[mt][nt], a[mt], bh[nt >> 1][(nt & 1) * 2],
                             bh[nt >> 1][(nt & 1) * 2 + 1]);
        }
        __syncthreads();
    }

    // epilogue: half2 stores to g_h
    const int erow = mBase + wy * 64 + (lane >> 2);
    const int ecol = nBase + wx * 32 + (lane & 3) * 2;
#pragma unroll
    for (int mt = 0; mt < 4; ++mt) {
#pragma unroll
        for (int nt = 0; nt < 4; ++nt) {
            int r0 = erow + mt * 16;
            int cc = ecol + nt * 8;
            if (r0 < NN) {
                __half2 p = __floats2half2_rn(c[mt][nt][0], c[mt][nt][1]);
                *(__half2*)&g_h[(size_t)r0 * DD + cc] = p;
            }
            if (r0 + 8 < NN) {
                __half2 p = __floats2half2_rn(c[mt][nt][2], c[mt][nt][3]);
                *(__half2*)&g_h[(size_t)(r0 + 8) * DD + cc] = p;
            }
        }
    }
}

// =================== aggregation (fp16 rows, 64 threads/node) ===================
__device__ __forceinline__ void fma_h8(float acc[8], uint4 v, float n) {
    __half2* hp = (__half2*)&v;
#pragma unroll
    for (int q = 0; q < 4; ++q) {
        float2 f = __half22float2(hp[q]);
        acc[q * 2 + 0] += f.x * n;
        acc[q * 2 + 1] += f.y * n;
    }
}

__global__ __launch_bounds__(64)
void agg_kernel(const float* __restrict__ bias,
                float* __restrict__ out) {
    const int i = blockIdx.x;
    const int t = threadIdx.x;          // 0..63, owns 8 columns
    const uint4* hb = (const uint4*)g_h;

    const float di = g_dinv[i];
    float acc[8];
    {
        const float4* bp = (const float4*)(bias + t * 8);
        float4 b0 = bp[0], b1 = bp[1];
        acc[0] = b0.x; acc[1] = b0.y; acc[2] = b0.z; acc[3] = b0.w;
        acc[4] = b1.x; acc[5] = b1.y; acc[6] = b1.z; acc[7] = b1.w;
    }
    // self loop
    fma_h8(acc, hb[(size_t)i * DV8 + t], di * di);

    int k = g_offsets[i];
    const int kend = g_offsets[i + 1];
    for (; k + 1 < kend; k += 2) {
        int r0 = g_esrc[k];
        int r1 = g_esrc[k + 1];
        float n0 = g_enorm[k];
        float n1 = g_enorm[k + 1];
        uint4 v0 = hb[(size_t)r0 * DV8 + t];
        uint4 v1 = hb[(size_t)r1 * DV8 + t];
        fma_h8(acc, v0, n0);
        fma_h8(acc, v1, n1);
    }
    if (k < kend) {
        fma_h8(acc, hb[(size_t)g_esrc[k] * DV8 + t], g_enorm[k]);
    }

    float4* op = (float4*)(out + (size_t)i * DD + t * 8);
    op[0] = make_float4(acc[0], acc[1], acc[2], acc[3]);
    op[1] = make_float4(acc[4], acc[5], acc[6], acc[7]);
}

// =================== launcher (fork-join: CSR chain overlaps prep+GEMM) ===================
extern "C" void kernel_launch(void* const* d_in, const int* in_sizes, int n_in,
                              void* d_out, int out_size) {
    const float* x    = (const float*)d_in[0];       // [NN, DD]
    const int*   eidx = (const int*)d_in[1];         // [2, EE] int32
    const float* ea   = (const float*)d_in[2];       // [EE]
    const float* W    = (const float*)d_in[3];       // [DD, DD]
    const float* b    = (const float*)d_in[4];       // [DD]
    float*       out  = (float*)d_out;               // [NN, DD]

    static cudaStream_t s2 = nullptr;
    static cudaEvent_t evFork = nullptr, evJoin = nullptr;
    if (s2 == nullptr) {
        cudaStreamCreateWithFlags(&s2, cudaStreamNonBlocking);
        cudaEventCreateWithFlags(&evFork, cudaEventDisableTiming);
        cudaEventCreateWithFlags(&evJoin, cudaEventDisableTiming);
        cudaFuncSetAttribute(gemm_kernel,
                             cudaFuncAttributeMaxDynamicSharedMemorySize, GEMM_SMEM);
    }

    // fork CSR chain onto s2 immediately (independent of prep/GEMM)
    cudaEventRecord(evFork, 0);
    cudaStreamWaitEvent(s2, evFork, 0);
    init_kernel<<<(NN + 255) / 256, 256, 0, s2>>>();
    deg_kernel<<<(EE + 255) / 256, 256, 0, s2>>>(eidx, ea);
    scan_kernel<<<1, 1024, 0, s2>>>();
    fill_kernel<<<(EE + 255) / 256, 256, 0, s2>>>(eidx, ea);
    cudaEventRecord(evJoin, s2);

    // main stream: prep then GEMM
    prep_kernel<<<5512, 256>>>(x, W);
    dim3 ggrid(DD / 128, (NN + 127) / 128);          // (4, 79)
    gemm_kernel<<<ggrid, 256, GEMM_SMEM>>>();

    // join, then aggregate
    cudaStreamWaitEvent(0, evJoin, 0);
    agg_kernel<<<NN, 64>>>(b, out);
}